// round 7
// baseline (speedup 1.0000x reference)
#include <cuda_runtime.h>
#include <cstdint>

// MoEVM_62380105007239 — soft-ALU over one-hot byte encodings.
// R7: per-warp 4-element software pipeline. Steady state per iteration:
//   issue element-i's 8 raw loads  ->  store element-(i-1)'s 4 KB output
//   (loads in flight behind the stores)  ->  decode element i.
// Each warp owns one sequential read stream and one sequential write
// stream, concurrently in flight for ~3/4 of its lifetime, maximizing
// read/write interleave at the DRAM controller.
//   pair g, role 0: reads a[e], writes add-output[e]
//   pair g, role 1: reads b[e], writes xor-output[e]
// Output values: 1.0 at result byte, exp(-100) (fp32 subnormal) at bytes
// sharing a nibble, 0 elsewhere — exactly what SCALE=100 softmax yields.

static __device__ __forceinline__ float onehot_val(int j, int s, float tiny) {
    if (j == s) return 1.0f;
    if (((j ^ s) & 0xF0) == 0 || ((j ^ s) & 0x0F) == 0) return tiny;
    return 0.0f;
}

// Decode 8 raw float4s (one-hot dot index == the index) into a packed u32.
static __device__ __forceinline__ unsigned decode_pack(const float4* x, int lane) {
    float acc[4] = {0.f, 0.f, 0.f, 0.f};
    #pragma unroll
    for (int r = 0; r < 8; r++) {
        const float j = (float)(lane * 4 + 128 * (r & 1));
        acc[r >> 1] += x[r].x * j + x[r].y * (j + 1.f)
                     + x[r].z * (j + 2.f) + x[r].w * (j + 3.f);
    }
    unsigned iv = (unsigned)(int)acc[0]
                | ((unsigned)(int)acc[1] << 8)
                | ((unsigned)(int)acc[2] << 16)
                | ((unsigned)(int)acc[3] << 24);
    return __reduce_or_sync(0xFFFFFFFFu, iv);
}

// Expand packed result to 4 KB near-one-hot output (8 coalesced STG.128).
static __device__ __forceinline__ void store_out(float4* dst, unsigned res, int lane) {
    const float TINY = 3.7200760e-44f;             // expf(-100), subnormal
    #pragma unroll
    for (int r = 0; r < 8; r++) {
        const int j  = lane * 4 + 128 * (r & 1);
        const int sb = (int)((res >> ((r >> 1) * 8)) & 255u);
        float4 o;
        o.x = onehot_val(j    , sb, TINY);
        o.y = onehot_val(j + 1, sb, TINY);
        o.z = onehot_val(j + 2, sb, TINY);
        o.w = onehot_val(j + 3, sb, TINY);
        __stcs(dst + lane + 32 * r, o);
    }
}

static constexpr int NE = 4;   // elements per warp-pair

__global__ void __launch_bounds__(256, 4) moe_alu_kernel(
    const float4* __restrict__ a4,
    const float4* __restrict__ b4,
    float4* __restrict__ o4,
    int B)
{
    __shared__ unsigned sm[2][4][2];          // [ping-pong][pair g][role]

    const int wid   = threadIdx.x >> 5;       // 0..7
    const int lane  = threadIdx.x & 31;
    const int g     = wid >> 1;               // pair id 0..3
    const int role  = wid & 1;                // 0: a/add-half, 1: b/xor-half
    const int ebase = blockIdx.x * (4 * NE) + g * NE;

    const float4* __restrict__ srcbase = (role == 0) ? a4 : b4;
    const size_t obase = (size_t)role * B;

    unsigned res_prev = 0;
    float4*  dst_prev = nullptr;

    #pragma unroll
    for (int i = 0; i < NE; i++) {
        const int e = ebase + i;
        const bool live = (e < B);

        // 1) Issue this element's raw loads first (long-scoreboard pending).
        float4 x[8];
        if (live) {
            const float4* __restrict__ src = srcbase + (size_t)e * 256;
            #pragma unroll
            for (int r = 0; r < 8; r++) x[r] = __ldcs(src + lane + 32 * r);
        }

        // 2) Store previous element's output while the loads are in flight.
        if (i > 0 && dst_prev) store_out(dst_prev, res_prev, lane);

        // 3) Decode this element and exchange bytes with the partner warp.
        if (live) {
            const unsigned v = decode_pack(x, lane);
            if (lane == 0) sm[i & 1][g][role] = v;
        }
        __syncthreads();                       // all warps iterate uniformly

        if (live) {
            const unsigned va = sm[i & 1][g][0];
            const unsigned vb = sm[i & 1][g][1];
            res_prev = (role == 0) ? (va + vb)   // LE carry chain == u32 add
                                   : (va ^ vb);  // bytewise xor
            dst_prev = o4 + (obase + e) * 256;
        } else {
            dst_prev = nullptr;
        }
    }

    // Drain: final element's stores.
    if (dst_prev) store_out(dst_prev, res_prev, lane);
}

extern "C" void kernel_launch(void* const* d_in, const int* in_sizes, int n_in,
                              void* d_out, int out_size)
{
    const float4* a = (const float4*)d_in[0];
    const float4* b = (const float4*)d_in[1];
    float4* out = (float4*)d_out;

    const int B = in_sizes[0] / 1024;            // inputs are [B,4,256]
    const int per_block = 4 * NE;                // 16 elements per block
    const int blocks = (B + per_block - 1) / per_block;
    moe_alu_kernel<<<blocks, 256>>>(a, b, out, B);
}

// round 8
// speedup vs baseline: 1.0161x; 1.0161x over previous
#include <cuda_runtime.h>
#include <cstdint>

// MoEVM_62380105007239 — soft-ALU over one-hot byte encodings.
// R8 (final polish of R6): 2-element pipeline per warp-pair with
// instruction-granular read/write interleave — element e1's loads are
// issued alternately with element e0's stores so the DRAM controller sees
// an evenly mixed R/W stream instead of alternating bursts.
//   pair g, role 0: reads a[e], writes add-output[e]
//   pair g, role 1: reads b[e], writes xor-output[e]
// Exact math: inputs are one-hot byte distributions; the SCALE=100 softmax
// pipeline reduces to u32 add (4-byte LE carry chain) and bytewise XOR.
// Output per byte slot: 1.0 at the result byte, exp(-100) (fp32 subnormal)
// at bytes sharing its high or low nibble, 0 elsewhere.

static __device__ __forceinline__ float onehot_val(int j, int s, float tiny) {
    if (j == s) return 1.0f;
    if (((j ^ s) & 0xF0) == 0 || ((j ^ s) & 0x0F) == 0) return tiny;
    return 0.0f;
}

// Decode 8 raw float4s (one-hot dot index == the index) into a packed u32.
static __device__ __forceinline__ unsigned decode_pack(const float4* x, int lane) {
    float acc[4] = {0.f, 0.f, 0.f, 0.f};
    #pragma unroll
    for (int r = 0; r < 8; r++) {
        const float j = (float)(lane * 4 + 128 * (r & 1));
        acc[r >> 1] += x[r].x * j + x[r].y * (j + 1.f)
                     + x[r].z * (j + 2.f) + x[r].w * (j + 3.f);
    }
    unsigned iv = (unsigned)(int)acc[0]
                | ((unsigned)(int)acc[1] << 8)
                | ((unsigned)(int)acc[2] << 16)
                | ((unsigned)(int)acc[3] << 24);
    return __reduce_or_sync(0xFFFFFFFFu, iv);
}

// One 16-byte output chunk of the near-one-hot expansion.
static __device__ __forceinline__ float4 out_chunk(unsigned res, int r, int lane) {
    const float TINY = 3.7200760e-44f;              // expf(-100), subnormal
    const int j  = lane * 4 + 128 * (r & 1);
    const int sb = (int)((res >> ((r >> 1) * 8)) & 255u);
    float4 o;
    o.x = onehot_val(j    , sb, TINY);
    o.y = onehot_val(j + 1, sb, TINY);
    o.z = onehot_val(j + 2, sb, TINY);
    o.w = onehot_val(j + 3, sb, TINY);
    return o;
}

__global__ void __launch_bounds__(256, 4) moe_alu_kernel(
    const float4* __restrict__ a4,
    const float4* __restrict__ b4,
    float4* __restrict__ o4,
    int B)
{
    __shared__ unsigned sm[2][4][2];          // [phase][pair g][role]

    const int wid  = threadIdx.x >> 5;        // 0..7
    const int lane = threadIdx.x & 31;
    const int g    = wid >> 1;                // pair id 0..3
    const int role = wid & 1;                 // 0: a/add-half, 1: b/xor-half
    const int e0   = blockIdx.x * 8 + g * 2;
    const int e1   = e0 + 1;
    if (e0 >= B) return;                      // block-uniform for full B
    const bool has1 = (e1 < B);

    const float4* __restrict__ srcbase = (role == 0) ? a4 : b4;
    const size_t obase = (size_t)role * B;

    // ── Phase 0: load + decode element e0 ──
    {
        const float4* __restrict__ s0 = srcbase + (size_t)e0 * 256;
        float4 x[8];
        #pragma unroll
        for (int r = 0; r < 8; r++) x[r] = __ldcs(s0 + lane + 32 * r);
        const unsigned v = decode_pack(x, lane);
        if (lane == 0) sm[0][g][role] = v;
    }
    __syncthreads();

    const unsigned va0 = sm[0][g][0];
    const unsigned vb0 = sm[0][g][1];
    const unsigned res0 = (role == 0) ? (va0 + vb0) : (va0 ^ vb0);

    // ── Interleaved: e1 loads alternate with e0 stores, instruction by
    //    instruction, so reads and writes mix evenly at the controller. ──
    const float4* __restrict__ s1 = srcbase + (size_t)e1 * 256;
    float4* __restrict__ d0 = o4 + (obase + e0) * 256;
    float4 x1[8];
    #pragma unroll
    for (int r = 0; r < 8; r++) {
        if (has1) x1[r] = __ldcs(s1 + lane + 32 * r);
        __stcs(d0 + lane + 32 * r, out_chunk(res0, r, lane));
    }

    // ── Phase 1: decode + store element e1 ──
    if (has1) {
        const unsigned v = decode_pack(x1, lane);
        if (lane == 0) sm[1][g][role] = v;
    }
    __syncthreads();

    if (has1) {
        const unsigned va1 = sm[1][g][0];
        const unsigned vb1 = sm[1][g][1];
        const unsigned res1 = (role == 0) ? (va1 + vb1) : (va1 ^ vb1);
        float4* __restrict__ d1 = o4 + (obase + e1) * 256;
        #pragma unroll
        for (int r = 0; r < 8; r++)
            __stcs(d1 + lane + 32 * r, out_chunk(res1, r, lane));
    }
}

extern "C" void kernel_launch(void* const* d_in, const int* in_sizes, int n_in,
                              void* d_out, int out_size)
{
    const float4* a = (const float4*)d_in[0];
    const float4* b = (const float4*)d_in[1];
    float4* out = (float4*)d_out;

    const int B = in_sizes[0] / 1024;      // inputs are [B,4,256] floats
    const int blocks = (B + 7) / 8;        // 8 elements per 8-warp block
    moe_alu_kernel<<<blocks, 256>>>(a, b, out, B);
}

// round 9
// speedup vs baseline: 1.0280x; 1.0116x over previous
#include <cuda_runtime.h>
#include <cstdint>

// MoEVM_62380105007239 — soft-ALU over one-hot byte encodings.
// R9: R6's proven-best structure (2-element depth-1 pipeline per warp pair,
// one sequential read stream + one sequential write stream per warp, batched
// loads THEN batched stores) upgraded to 256-bit global ld/st (sm_100+
// LDG.E.256 / STG.E.256): half the memory instructions, 1KB coalesced
// bursts, and slot index uniform per chunk (slot == chunk id r).
//   pair g, role 0: reads a[e], writes add-output[e]
//   pair g, role 1: reads b[e], writes xor-output[e]
// Exact math: inputs are one-hot byte distributions; the SCALE=100 softmax
// pipeline reduces to u32 add (4-byte LE carry chain) and bytewise XOR.
// Output per byte slot: 1.0 at the result byte, exp(-100) (fp32 subnormal)
// at bytes sharing its high or low nibble, 0 elsewhere.

static __device__ __forceinline__ void ldg256(float* v, const float* p) {
    asm volatile(
        "ld.global.cs.v8.f32 {%0,%1,%2,%3,%4,%5,%6,%7}, [%8];"
        : "=f"(v[0]), "=f"(v[1]), "=f"(v[2]), "=f"(v[3]),
          "=f"(v[4]), "=f"(v[5]), "=f"(v[6]), "=f"(v[7])
        : "l"(p));
}

static __device__ __forceinline__ void stg256(float* p, const float* v) {
    asm volatile(
        "st.global.cs.v8.f32 [%0], {%1,%2,%3,%4,%5,%6,%7,%8};"
        :: "l"(p),
           "f"(v[0]), "f"(v[1]), "f"(v[2]), "f"(v[3]),
           "f"(v[4]), "f"(v[5]), "f"(v[6]), "f"(v[7])
        : "memory");
}

static __device__ __forceinline__ float onehot_val(int j, int s, float tiny) {
    if (j == s) return 1.0f;
    if (((j ^ s) & 0xF0) == 0 || ((j ^ s) & 0x0F) == 0) return tiny;
    return 0.0f;
}

// Decode 4 chunks of 8 floats (chunk r == byte slot r; lane covers byte
// indices lane*8 .. lane*8+7). One-hot dot index == the index; index 0
// contributes 0, which is correct for the OR-pack.
static __device__ __forceinline__ unsigned decode_pack(const float x[4][8], int lane) {
    const float jb = (float)(lane * 8);
    unsigned iv = 0;
    #pragma unroll
    for (int r = 0; r < 4; r++) {
        float acc = 0.f;
        #pragma unroll
        for (int c = 0; c < 8; c++) acc += x[r][c] * (jb + (float)c);
        iv |= (unsigned)(int)acc << (8 * r);
    }
    return __reduce_or_sync(0xFFFFFFFFu, iv);
}

// Expand packed result to 4 KB near-one-hot output (4 x STG.256).
static __device__ __forceinline__ void store_out(float* dst, unsigned res, int lane) {
    const float TINY = 3.7200760e-44f;              // expf(-100), subnormal
    const int jb = lane * 8;
    #pragma unroll
    for (int r = 0; r < 4; r++) {
        const int sb = (int)((res >> (8 * r)) & 255u);
        float o[8];
        #pragma unroll
        for (int c = 0; c < 8; c++) o[c] = onehot_val(jb + c, sb, TINY);
        stg256(dst + lane * 8 + 256 * r, o);
    }
}

__global__ void __launch_bounds__(256, 4) moe_alu_kernel(
    const float* __restrict__ a,
    const float* __restrict__ b,
    float* __restrict__ out,
    int B)
{
    __shared__ unsigned sm[2][4][2];          // [phase][pair g][role]

    const int wid  = threadIdx.x >> 5;        // 0..7
    const int lane = threadIdx.x & 31;
    const int g    = wid >> 1;                // pair id 0..3
    const int role = wid & 1;                 // 0: a/add-half, 1: b/xor-half
    const int e0   = blockIdx.x * 8 + g * 2;
    const int e1   = e0 + 1;
    if (e0 >= B) return;                      // block-uniform for full B
    const bool has1 = (e1 < B);

    const float* __restrict__ srcbase = (role == 0) ? a : b;
    const size_t obase = (size_t)role * B;

    // ── Phase 0: load + decode element e0 (4 batched LDG.256) ──
    {
        const float* __restrict__ s0 = srcbase + (size_t)e0 * 1024;
        float x[4][8];
        #pragma unroll
        for (int r = 0; r < 4; r++) ldg256(x[r], s0 + lane * 8 + 256 * r);
        const unsigned v = decode_pack(x, lane);
        if (lane == 0) sm[0][g][role] = v;
    }
    __syncthreads();

    const unsigned va0 = sm[0][g][0];
    const unsigned vb0 = sm[0][g][1];
    const unsigned res0 = (role == 0) ? (va0 + vb0)   // LE carry == u32 add
                                      : (va0 ^ vb0);  // bytewise xor

    // ── Prefetch e1's raw loads (batched, front-loaded MLP), then store
    //    e0's output while they are in flight. ──
    float x1[4][8];
    if (has1) {
        const float* __restrict__ s1 = srcbase + (size_t)e1 * 1024;
        #pragma unroll
        for (int r = 0; r < 4; r++) ldg256(x1[r], s1 + lane * 8 + 256 * r);
    }
    store_out(out + (obase + e0) * 1024, res0, lane);

    // ── Phase 1: decode + store element e1 ──
    if (has1) {
        const unsigned v = decode_pack(x1, lane);
        if (lane == 0) sm[1][g][role] = v;
    }
    __syncthreads();

    if (has1) {
        const unsigned va1 = sm[1][g][0];
        const unsigned vb1 = sm[1][g][1];
        const unsigned res1 = (role == 0) ? (va1 + vb1) : (va1 ^ vb1);
        store_out(out + (obase + e1) * 1024, res1, lane);
    }
}

extern "C" void kernel_launch(void* const* d_in, const int* in_sizes, int n_in,
                              void* d_out, int out_size)
{
    const float* a = (const float*)d_in[0];
    const float* b = (const float*)d_in[1];
    float* out = (float*)d_out;

    const int B = in_sizes[0] / 1024;      // inputs are [B,4,256] floats
    const int blocks = (B + 7) / 8;        // 8 elements per 8-warp block
    moe_alu_kernel<<<blocks, 256>>>(a, b, out, B);
}